// round 1
// baseline (speedup 1.0000x reference)
#include <cuda_runtime.h>
#include <math.h>

// Problem constants (from reference)
#define C_NX 120
#define C_B  8
#define C_J  22
#define C_F  14      // features per player row
#define A_MAX 7.25f
#define S_MAX 9.25f
// sigmoid steepness: 3.14 / (1.732 * 0.5)
#define SIG_K (3.14f / (1.732f * 0.5f))

// Key insight: the reference materializes p_int over (B, 6600 field cells,
// 40 T steps, 22 players) but the output gathers exactly ONE field cell,
// ONE T index, and (after the defender-product over J) ONE attacker per
// batch. Only B*J = 176 sigmoid terms are live.
//
// frame column map: 0=idx 1=px 2=py 3=vx 4=vy 5=ax 6=ay 7=team
//                   8=bc(px0) 9=bc(py0) 10=rec(one-hot) 11=bx 12=by 13=tof
// REAX_T = 0 -> x_r = px, v_r = v. TTI_EPS = 0. lambda_off = 1 (identity).

__global__ void comp_prob_kernel(const float* __restrict__ frame,
                                 float* __restrict__ out) {
    __shared__ float q[C_B][C_J];     // 1 - p_int * (1 - team)  (defender term)
    __shared__ float patt[C_B][C_J];  // p_int * team            (attacker term)

    const int tid = threadIdx.x;

    if (tid < C_B * C_J) {
        const int b = tid / C_J;
        const int j = tid % C_J;
        const float* row  = frame + (b * C_J + j) * C_F;
        const float* row0 = frame + (b * C_J) * C_F;

        const float px = row[1], py = row[2];
        const float vx = row[3], vy = row[4];
        const float team = row[7];

        // Field cell selected by the final gather:
        //   ix = int(bx), iy = int(by) + 1
        //   x[ix] = ix + 0.5 (linspace 0.5..119.5, step 1)
        //   y[iy] = iy - 0.5 (linspace -0.5..53.5, step 1; iy >= 3 so the
        //                     y[0] = -0.2 patch is never hit)
        const int ix = (int)row0[11];
        const int iy = (int)row0[12] + 1;
        const float fx = (float)ix + 0.5f;
        const float fy = (float)iy - 0.5f;

        const float dx = fx - px;
        const float dy = fy - py;
        const float d  = sqrtf(dx * dx + dy * dy);

        float s0 = (dx * vx + dy * vy) / d;
        s0 = fminf(fmaxf(s0, -S_MAX), S_MAX);

        float t_lt = (S_MAX - s0) / A_MAX;
        float d_lt = t_lt * (s0 + S_MAX) * 0.5f;
        if (d_lt > d) {
            const float sa = s0 / A_MAX;
            t_lt = -sa + sqrtf(sa * sa + 2.0f * d / A_MAX);
        }
        d_lt = fminf(fmaxf(d_lt, 0.0f), d);
        const float t_at  = (d - d_lt) / S_MAX;
        const float t_tot = t_lt + t_at;   // REAX_T = 0

        // T index selected by the gather: round(tof) - 1 ; T[t] = 0.1*(t+1)
        const int   ti = (int)rintf(row0[13]) - 1;
        const float Tt = 0.1f + 0.1f * (float)ti;

        const float p = 1.0f / (1.0f + expf(-SIG_K * (Tt - t_tot)));

        q[b][j]    = 1.0f - p * (1.0f - team);
        patt[b][j] = p * team;
    }
    __syncthreads();

    if (tid < C_B) {
        const int b = tid;
        // prod = prod_j (1 - p_j * (1 - team_j)) = 1 - p_int_def
        float prod = 1.0f;
        // pm = argmax_j rec[j] * (J - j)  (first-max semantics like jnp.argmax)
        int   jm   = 0;
        float best = -1.0f;
        #pragma unroll
        for (int j = 0; j < C_J; ++j) {
            prod *= q[b][j];
            const float v = frame[(b * C_J + j) * C_F + 10] * (float)(C_J - j);
            if (v > best) { best = v; jm = j; }
        }
        // p_int_adj[jm] = p * (1 - p_def) * team ; lambda_off = 1 -> identity
        out[b] = patt[b][jm] * prod + 0.001f;
    }
}

extern "C" void kernel_launch(void* const* d_in, const int* in_sizes, int n_in,
                              void* d_out, int out_size) {
    const float* frame = (const float*)d_in[0];
    float* out = (float*)d_out;
    comp_prob_kernel<<<1, 256>>>(frame, out);
}

// round 2
// speedup vs baseline: 1.2313x; 1.2313x over previous
#include <cuda_runtime.h>
#include <math.h>

#define C_B  8
#define C_J  22
#define C_F  14
#define A_MAX 7.25f
#define S_MAX 9.25f
#define SIG_K (3.14f / (1.732f * 0.5f))

// One warp per batch. Lane j computes the (b,j) sigmoid term; lanes >= 22
// carry neutral values. The reference's argmax-over-one-hot gather is a dot
// product with rec, so the epilogue is a simultaneous (product, sum)
// warp-shuffle butterfly: out[b] = (sum_j rec_j*p_j*team_j) * prod_j(1 - p_j*(1-team_j)) + 1e-3.
__global__ void comp_prob_kernel(const float* __restrict__ frame,
                                 float* __restrict__ out) {
    const int b = threadIdx.x >> 5;   // warp id = batch
    const int j = threadIdx.x & 31;   // lane = player

    float q = 1.0f;   // defender term: 1 - p*(1-team)
    float s = 0.0f;   // attacker gather term: rec * p * team

    const float* row0 = frame + b * C_J * C_F;

    if (j < C_J) {
        const float* row = row0 + j * C_F;

        const float px = row[1], py = row[2];
        const float vx = row[3], vy = row[4];
        const float team = row[7];
        const float rec  = row[10];

        // Selected field cell: x = int(bx)+0.5, y = (int(by)+1)-0.5
        const float fx = (float)((int)row0[11]) + 0.5f;
        const float fy = (float)((int)row0[12] + 1) - 0.5f;

        const float dx = fx - px;
        const float dy = fy - py;
        const float d  = sqrtf(dx * dx + dy * dy);

        float s0 = (dx * vx + dy * vy) / d;
        s0 = fminf(fmaxf(s0, -S_MAX), S_MAX);

        float t_lt = (S_MAX - s0) * (1.0f / A_MAX);
        float d_lt = t_lt * (s0 + S_MAX) * 0.5f;
        if (d_lt > d) {
            const float sa = s0 * (1.0f / A_MAX);
            t_lt = -sa + sqrtf(sa * sa + 2.0f * d * (1.0f / A_MAX));
        }
        d_lt = fminf(fmaxf(d_lt, 0.0f), d);
        const float t_tot = t_lt + (d - d_lt) * (1.0f / S_MAX);

        // Selected T: t = round(tof)-1 ; T[t] = 0.1*(t+1) = 0.1*round(tof)
        const float Tt = 0.1f * rintf(row0[13]);

        const float p = 1.0f / (1.0f + __expf(-SIG_K * (Tt - t_tot)));

        q = 1.0f - p * (1.0f - team);
        s = rec * p * team;
    }

    // Simultaneous product/sum butterfly across the warp.
    #pragma unroll
    for (int o = 16; o > 0; o >>= 1) {
        q *= __shfl_xor_sync(0xFFFFFFFFu, q, o);
        s += __shfl_xor_sync(0xFFFFFFFFu, s, o);
    }

    if (j == 0) out[b] = s * q + 0.001f;
}

extern "C" void kernel_launch(void* const* d_in, const int* in_sizes, int n_in,
                              void* d_out, int out_size) {
    comp_prob_kernel<<<1, C_B * 32>>>((const float*)d_in[0], (float*)d_out);
}